// round 6
// baseline (speedup 1.0000x reference)
#include <cuda_runtime.h>
#include <math.h>

#define BB 16
#define CC 3
#define HH 512
#define WW 512
#define HWv (HH*WW)

#define ROWS 16
#define NBANDS (HH/ROWS)      // 32
#define NT 512                // one thread per x-column
#define NBLOCKS (BB*NBANDS)   // 512

#define IRBLK 32              // ir-mean blocks per batch
#define NIRB (BB*IRBLK)       // 512

__device__ double g_ir_part[NIRB];   // per-block gray sums of input_ir
__device__ float  g_part[NBLOCKS];   // per-block loss partials

// ---------------------------------------------------------------------------
// 1) per-batch gray sum of input_ir, float4 vectorized, no atomics/no init:
//    each block writes its own partial.  gray = 0.2989 R + 0.587 G + 0.114 B
// ---------------------------------------------------------------------------
__global__ __launch_bounds__(256)
void ir_mean_kernel(const float4* __restrict__ ir) {
    int b   = blockIdx.x / IRBLK;
    int blk = blockIdx.x % IRBLK;
    const int q4  = HWv / 4;        // float4 per plane
    const int per = q4 / IRBLK;     // 2048 float4 per block

    size_t base = (size_t)b * CC * q4 + (size_t)blk * per;
    const float4* r  = ir + base;
    const float4* g  = r + q4;
    const float4* bl = g + q4;

    float s = 0.f;
    for (int i = threadIdx.x; i < per; i += 256) {
        float4 a = r[i], c = g[i], d = bl[i];
        s += 0.2989f * (a.x + a.y + a.z + a.w)
           + 0.587f  * (c.x + c.y + c.z + c.w)
           + 0.114f  * (d.x + d.y + d.z + d.w);
    }
    #pragma unroll
    for (int o = 16; o; o >>= 1) s += __shfl_down_sync(0xffffffffu, s, o);

    __shared__ float ws[8];
    int wid = threadIdx.x >> 5, lid = threadIdx.x & 31;
    if (lid == 0) ws[wid] = s;
    __syncthreads();
    if (wid == 0) {
        s = (lid < 8) ? ws[lid] : 0.f;
        #pragma unroll
        for (int o = 4; o; o >>= 1) s += __shfl_down_sync(0xffffffffu, s, o);
        if (lid == 0) g_ir_part[blockIdx.x] = (double)s;
    }
}

// ---------------------------------------------------------------------------
// 2) main fused pass: register-streaming vertical stencil, smem only for
//    horizontal T/S exchange (ping-pong, one sync per channel-row).
// ---------------------------------------------------------------------------
__global__ __launch_bounds__(NT, 2)
void fusion_main_kernel(const float* __restrict__ vis,
                        const float* __restrict__ ir,
                        const float* __restrict__ outp,
                        const float* __restrict__ mask) {
    __shared__ float buf[2][6][WW + 2];   // [parity][TF,SF,TV,SV,TI,SI][x+1]
    __shared__ float s_mean;

    const int x    = threadIdx.x;
    const int b    = blockIdx.x / NBANDS;
    const int band = blockIdx.x % NBANDS;
    const int y0   = band * ROWS;

    // zero the padding columns (x = -1 and x = 512 of the image)
    if (x < 24) {
        int p = x / 12, a = (x % 12) / 2, e = x & 1;
        buf[p][a][e ? (WW + 1) : 0] = 0.f;
    }
    if (x == 0) {
        double s = 0.0;
        #pragma unroll
        for (int i = 0; i < IRBLK; i++) s += g_ir_part[b * IRBLK + i];
        s_mean = (float)(s * (1.0 / (double)HWv));
    }
    __syncthreads();
    const float meanb = s_mean;

    const size_t bbase = (size_t)b * CC * HWv + x;

    float pF[3], qF[3], pV[3], qV[3], pI[3], qI[3];

    // prologue: rows y0-1 (zero pad if OOB) and y0
    #pragma unroll
    for (int c = 0; c < CC; c++) {
        if (y0 > 0) {
            size_t pp = bbase + (size_t)c * HWv + (size_t)(y0 - 1) * WW;
            pF[c] = outp[pp] * mask[pp];
            pV[c] = fminf(fmaxf(sqrtf(vis[pp]), 0.f), 1.f);
            pI[c] = fminf(fmaxf(1.8f * ir[pp] - 0.8f * meanb, 0.f), 1.f);
        } else { pF[c] = pV[c] = pI[c] = 0.f; }
        {
            size_t pp = bbase + (size_t)c * HWv + (size_t)y0 * WW;
            qF[c] = outp[pp] * mask[pp];
            qV[c] = fminf(fmaxf(sqrtf(vis[pp]), 0.f), 1.f);
            qI[c] = fminf(fmaxf(1.8f * ir[pp] - 0.8f * meanb, 0.f), 1.f);
        }
    }

    float con = 0.f, gsum = 0.f, color = 0.f;
    int parity = 0;

    for (int yi = 0; yi < ROWS; yi++) {
        const int y = y0 + yi;
        float cF[3], cV[3];
        #pragma unroll
        for (int c = 0; c < CC; c++) {
            // load row y+1 (zero pad at image bottom)
            float nF, nV, nI;
            if (y + 1 < HH) {
                size_t pp = bbase + (size_t)c * HWv + (size_t)(y + 1) * WW;
                nF = outp[pp] * mask[pp];
                nV = fminf(fmaxf(sqrtf(vis[pp]), 0.f), 1.f);
                nI = fminf(fmaxf(1.8f * ir[pp] - 0.8f * meanb, 0.f), 1.f);
            } else { nF = nV = nI = 0.f; }

            // vertical Sobel partials in registers
            float TF = pF[c] + 2.f * qF[c] + nF,  SF = pF[c] - nF;
            float TV = pV[c] + 2.f * qV[c] + nV,  SV = pV[c] - nV;
            float TI = pI[c] + 2.f * qI[c] + nI,  SI = pI[c] - nI;

            float (*B)[WW + 2] = buf[parity];
            B[0][x + 1] = TF;  B[1][x + 1] = SF;
            B[2][x + 1] = TV;  B[3][x + 1] = SV;
            B[4][x + 1] = TI;  B[5][x + 1] = SI;
            __syncthreads();

            // gx = T[x+1]-T[x-1] ; gy = S[x-1]+2S[x]+S[x+1]
            float fgx = B[0][x + 2] - B[0][x];
            float vgx = B[2][x + 2] - B[2][x];
            float igx = B[4][x + 2] - B[4][x];
            float fgy = B[1][x] + 2.f * SF + B[1][x + 2];
            float vgy = B[3][x] + 2.f * SV + B[3][x + 2];
            float igy = B[5][x] + 2.f * SI + B[5][x + 2];

            gsum += fabsf(fgx - fmaxf(vgx, igx)) + fabsf(fgy - fmaxf(vgy, igy));
            con  += fabsf(qF[c] - fmaxf(qV[c], qI[c]));
            cF[c] = qF[c];  cV[c] = qV[c];

            pF[c] = qF[c];  qF[c] = nF;
            pV[c] = qV[c];  qV[c] = nV;
            pI[c] = qI[c];  qI[c] = nI;
            parity ^= 1;
        }
        // chroma diffs (the +0.5 cancels)
        float YF = 0.299f * cF[0] + 0.587f * cF[1] + 0.114f * cF[2];
        float YV = 0.299f * cV[0] + 0.587f * cV[1] + 0.114f * cV[2];
        color += fabsf((cF[2] - YF) * 0.564f - (cV[2] - YV) * 0.564f)
               + fabsf((cF[0] - YF) * 0.713f - (cV[0] - YV) * 0.713f);
    }

    const float inv3 = 1.0f / (float)(BB * CC * HWv);
    const float inv1 = 1.0f / (float)(BB * HWv);
    float acc = inv3 * (0.5f * con + 0.1f * gsum) + inv1 * color;

    // block reduction -> per-block partial (no atomics)
    #pragma unroll
    for (int o = 16; o; o >>= 1) acc += __shfl_down_sync(0xffffffffu, acc, o);
    __shared__ float ws[NT / 32];
    int wid = x >> 5, lid = x & 31;
    if (lid == 0) ws[wid] = acc;
    __syncthreads();
    if (wid == 0) {
        acc = (lid < NT / 32) ? ws[lid] : 0.f;
        #pragma unroll
        for (int o = 8; o; o >>= 1) acc += __shfl_down_sync(0xffffffffu, acc, o);
        if (lid == 0) g_part[blockIdx.x] = acc;
    }
}

// ---------------------------------------------------------------------------
// 3) finalize: sum the 512 block partials in double, write scalar
// ---------------------------------------------------------------------------
__global__ __launch_bounds__(NT)
void finalize_kernel(float* __restrict__ out) {
    int t = threadIdx.x;
    double s = (double)g_part[t];
    #pragma unroll
    for (int o = 16; o; o >>= 1) s += __shfl_down_sync(0xffffffffu, s, o);
    __shared__ double ws[NT / 32];
    int wid = t >> 5, lid = t & 31;
    if (lid == 0) ws[wid] = s;
    __syncthreads();
    if (wid == 0) {
        s = (lid < NT / 32) ? ws[lid] : 0.0;
        #pragma unroll
        for (int o = 8; o; o >>= 1) s += __shfl_down_sync(0xffffffffu, s, o);
        if (lid == 0) out[0] = (float)s;
    }
}

extern "C" void kernel_launch(void* const* d_in, const int* in_sizes, int n_in,
                              void* d_out, int out_size) {
    const float* vis  = (const float*)d_in[0];
    const float* ir   = (const float*)d_in[1];
    const float* outp = (const float*)d_in[2];
    const float* mask = (const float*)d_in[3];
    float* out = (float*)d_out;

    ir_mean_kernel<<<NIRB, 256>>>((const float4*)ir);
    fusion_main_kernel<<<NBLOCKS, NT>>>(vis, ir, outp, mask);
    finalize_kernel<<<1, NT>>>(out);
}

// round 8
// speedup vs baseline: 1.6235x; 1.6235x over previous
#include <cuda_runtime.h>
#include <math.h>

#define BB 16
#define CC 3
#define HH 512
#define WW 512
#define HWv (HH*WW)

#define TXW 128
#define TYH 16
#define XT (WW/TXW)          // 4
#define YT (HH/TYH)          // 32
#define NBLK (BB*XT*YT)      // 2048
#define NT 512
#define PITCH 136            // cols: 3 = x-1 halo, 4..131 interior, 132 = x+128 halo

#define IRBLK 64
#define NIRB (BB*IRBLK)      // 1024

__device__ double g_ir_part[NIRB];
__device__ float  g_part[NBLK];

// ---------------------------------------------------------------------------
// 1) per-batch gray sum of input_ir. gray = 0.2989 R + 0.587 G + 0.114 B
// ---------------------------------------------------------------------------
__global__ __launch_bounds__(256)
void ir_mean_kernel(const float4* __restrict__ ir) {
    int b   = blockIdx.x / IRBLK;
    int blk = blockIdx.x % IRBLK;
    const int q4  = HWv / 4;          // 65536 float4 per plane
    const int per = q4 / IRBLK;       // 1024 float4 per block

    size_t base = (size_t)b * CC * q4 + (size_t)blk * per;
    const float4* r  = ir + base;
    const float4* g  = r + q4;
    const float4* bl = g + q4;

    float s = 0.f;
    #pragma unroll
    for (int i = threadIdx.x; i < per; i += 256) {
        float4 a = r[i], c = g[i], d = bl[i];
        s += 0.2989f * (a.x + a.y + a.z + a.w)
           + 0.587f  * (c.x + c.y + c.z + c.w)
           + 0.114f  * (d.x + d.y + d.z + d.w);
    }
    #pragma unroll
    for (int o = 16; o; o >>= 1) s += __shfl_down_sync(0xffffffffu, s, o);

    __shared__ float ws[8];
    int wid = threadIdx.x >> 5, lid = threadIdx.x & 31;
    if (lid == 0) ws[wid] = s;
    __syncthreads();
    if (wid == 0) {
        s = (lid < 8) ? ws[lid] : 0.f;
        #pragma unroll
        for (int o = 4; o; o >>= 1) s += __shfl_down_sync(0xffffffffu, s, o);
        if (lid == 0) g_ir_part[blockIdx.x] = (double)s;
    }
}

__device__ __forceinline__ float clip01(float x) {
    return fminf(fmaxf(x, 0.f), 1.f);
}

// ---------------------------------------------------------------------------
// 2) fused main pass: 128x16 aligned float4 tiles, channels sequential
//    (2 syncs/channel), per-thread 4 consecutive rows with rolling windows.
// ---------------------------------------------------------------------------
__global__ __launch_bounds__(NT, 2)
void fusion_main_kernel(const float* __restrict__ vis,
                        const float* __restrict__ ir,
                        const float* __restrict__ outp,
                        const float* __restrict__ mask) {
    __shared__ float sF[TYH + 2][PITCH];
    __shared__ float sV[TYH + 2][PITCH];
    __shared__ float sI[TYH + 2][PITCH];
    __shared__ double dred[2];
    __shared__ float s_mean;
    __shared__ float ws[NT / 32];

    const int tid = threadIdx.x;
    const int bx  = blockIdx.x;
    const int b   = bx >> 7;              // 128 tiles per batch
    const int rem = bx & 127;
    const int y0  = (rem >> 2) * TYH;
    const int w0  = (rem & 3) * TXW;

    // per-batch IR mean from 64 partials
    if (tid < IRBLK) {
        double s = g_ir_part[b * IRBLK + tid];
        #pragma unroll
        for (int o = 16; o; o >>= 1) s += __shfl_down_sync(0xffffffffu, s, o);
        if ((tid & 31) == 0) dred[tid >> 5] = s;
    }
    __syncthreads();
    if (tid == 0) s_mean = (float)((dred[0] + dred[1]) * (1.0 / (double)HWv));
    __syncthreads();
    const float meanb = s_mean;

    const int dx = tid & 127;             // x within tile
    const int rg = tid >> 7;              // rowgroup 0..3 -> rows 4rg..4rg+3
    const int cm = dx + 4;                // smem mid column
    const int hb = rg * 4;                // first window smem row

    float con = 0.f, gsum = 0.f, color = 0.f;
    float d0[4], dyk[4];

    #pragma unroll
    for (int c = 0; c < CC; c++) {
        const size_t pbase = ((size_t)b * CC + c) * HWv;

        // -------- load 18x128 interior (float4) + 18x2 halo scalars --------
        for (int idx = tid; idx < 612; idx += NT) {
            if (idx < 576) {
                int hy = idx >> 5, k = idx & 31;
                int y = y0 - 1 + hy;
                float4 f = make_float4(0.f, 0.f, 0.f, 0.f), v = f, q = f;
                if ((unsigned)y < HH) {
                    size_t rowp = pbase + (size_t)y * WW + w0;
                    float4 a  = ((const float4*)(outp + rowp))[k];
                    float4 m  = ((const float4*)(mask + rowp))[k];
                    float4 vv = ((const float4*)(vis  + rowp))[k];
                    float4 qq = ((const float4*)(ir   + rowp))[k];
                    f = make_float4(a.x * m.x, a.y * m.y, a.z * m.z, a.w * m.w);
                    v = make_float4(clip01(sqrtf(vv.x)), clip01(sqrtf(vv.y)),
                                    clip01(sqrtf(vv.z)), clip01(sqrtf(vv.w)));
                    q = make_float4(clip01(1.8f * qq.x - 0.8f * meanb),
                                    clip01(1.8f * qq.y - 0.8f * meanb),
                                    clip01(1.8f * qq.z - 0.8f * meanb),
                                    clip01(1.8f * qq.w - 0.8f * meanb));
                }
                *(float4*)&sF[hy][4 + 4 * k] = f;
                *(float4*)&sV[hy][4 + 4 * k] = v;
                *(float4*)&sI[hy][4 + 4 * k] = q;
            } else {
                int j = idx - 576;
                int hy = j >> 1, side = j & 1;
                int y = y0 - 1 + hy;
                int x = side ? (w0 + TXW) : (w0 - 1);
                float f = 0.f, v = 0.f, q = 0.f;
                if ((unsigned)y < HH && (unsigned)x < WW) {
                    size_t p = pbase + (size_t)y * WW + x;
                    f = outp[p] * mask[p];
                    v = clip01(sqrtf(vis[p]));
                    q = clip01(1.8f * ir[p] - 0.8f * meanb);
                }
                int cp = side ? (4 + TXW) : 3;
                sF[hy][cp] = f; sV[hy][cp] = v; sI[hy][cp] = q;
            }
        }
        __syncthreads();

        // -------- compute: rolling 3x3 windows over rows hb..hb+5 --------
        float wF[3][3], wV[3][3], wI[3][3];
        #pragma unroll
        for (int r = 0; r < 2; r++) {
            wF[r][0] = sF[hb + r][cm - 1]; wF[r][1] = sF[hb + r][cm]; wF[r][2] = sF[hb + r][cm + 1];
            wV[r][0] = sV[hb + r][cm - 1]; wV[r][1] = sV[hb + r][cm]; wV[r][2] = sV[hb + r][cm + 1];
            wI[r][0] = sI[hb + r][cm - 1]; wI[r][1] = sI[hb + r][cm]; wI[r][2] = sI[hb + r][cm + 1];
        }
        #pragma unroll
        for (int k = 0; k < 4; k++) {
            const int rp = k % 3, rq = (k + 1) % 3, rn = (k + 2) % 3;
            const int hy = hb + k + 2;
            wF[rn][0] = sF[hy][cm - 1]; wF[rn][1] = sF[hy][cm]; wF[rn][2] = sF[hy][cm + 1];
            wV[rn][0] = sV[hy][cm - 1]; wV[rn][1] = sV[hy][cm]; wV[rn][2] = sV[hy][cm + 1];
            wI[rn][0] = sI[hy][cm - 1]; wI[rn][1] = sI[hy][cm]; wI[rn][2] = sI[hy][cm + 1];

            // gx = colsum[1,2,1](x+1) - colsum[1,2,1](x-1)
            float fgx = (wF[rp][2] + 2.f * wF[rq][2] + wF[rn][2]) - (wF[rp][0] + 2.f * wF[rq][0] + wF[rn][0]);
            float vgx = (wV[rp][2] + 2.f * wV[rq][2] + wV[rn][2]) - (wV[rp][0] + 2.f * wV[rq][0] + wV[rn][0]);
            float igx = (wI[rp][2] + 2.f * wI[rq][2] + wI[rn][2]) - (wI[rp][0] + 2.f * wI[rq][0] + wI[rn][0]);
            // gy = (p-n)(x-1) + 2(p-n)(x) + (p-n)(x+1)
            float fgy = (wF[rp][0] - wF[rn][0]) + 2.f * (wF[rp][1] - wF[rn][1]) + (wF[rp][2] - wF[rn][2]);
            float vgy = (wV[rp][0] - wV[rn][0]) + 2.f * (wV[rp][1] - wV[rn][1]) + (wV[rp][2] - wV[rn][2]);
            float igy = (wI[rp][0] - wI[rn][0]) + 2.f * (wI[rp][1] - wI[rn][1]) + (wI[rp][2] - wI[rn][2]);

            gsum += fabsf(fgx - fmaxf(vgx, igx)) + fabsf(fgy - fmaxf(vgy, igy));

            float Fc = wF[rq][1], Vc = wV[rq][1];
            con += fabsf(Fc - fmaxf(Vc, wI[rq][1]));

            // chroma via linear-combination carry:
            // Cb_F-Cb_V = 0.564*((F2-V2) - dY), Cr_F-Cr_V = 0.713*((F0-V0) - dY)
            float d = Fc - Vc;
            if (c == 0)      { d0[k] = d; dyk[k] = 0.299f * d; }
            else if (c == 1) { dyk[k] += 0.587f * d; }
            else {
                float dyt = dyk[k] + 0.114f * d;
                color += fabsf(0.564f * (d - dyt)) + fabsf(0.713f * (d0[k] - dyt));
            }
        }
        __syncthreads();
    }

    const float inv3 = 1.0f / (float)(BB * CC * HWv);
    const float inv1 = 1.0f / (float)(BB * HWv);
    float acc = inv3 * (0.5f * con + 0.1f * gsum) + inv1 * color;

    #pragma unroll
    for (int o = 16; o; o >>= 1) acc += __shfl_down_sync(0xffffffffu, acc, o);
    int wid = tid >> 5, lid = tid & 31;
    if (lid == 0) ws[wid] = acc;
    __syncthreads();
    if (wid == 0) {
        acc = (lid < NT / 32) ? ws[lid] : 0.f;
        #pragma unroll
        for (int o = 8; o; o >>= 1) acc += __shfl_down_sync(0xffffffffu, acc, o);
        if (lid == 0) g_part[blockIdx.x] = acc;
    }
}

// ---------------------------------------------------------------------------
// 3) finalize: sum 2048 block partials in double
// ---------------------------------------------------------------------------
__global__ __launch_bounds__(NT)
void finalize_kernel(float* __restrict__ out) {
    int t = threadIdx.x;
    double s = 0.0;
    #pragma unroll
    for (int i = 0; i < NBLK / NT; i++) s += (double)g_part[t + i * NT];
    #pragma unroll
    for (int o = 16; o; o >>= 1) s += __shfl_down_sync(0xffffffffu, s, o);
    __shared__ double ws[NT / 32];
    int wid = t >> 5, lid = t & 31;
    if (lid == 0) ws[wid] = s;
    __syncthreads();
    if (wid == 0) {
        s = (lid < NT / 32) ? ws[lid] : 0.0;
        #pragma unroll
        for (int o = 8; o; o >>= 1) s += __shfl_down_sync(0xffffffffu, s, o);
        if (lid == 0) out[0] = (float)s;
    }
}

extern "C" void kernel_launch(void* const* d_in, const int* in_sizes, int n_in,
                              void* d_out, int out_size) {
    const float* vis  = (const float*)d_in[0];
    const float* ir   = (const float*)d_in[1];
    const float* outp = (const float*)d_in[2];
    const float* mask = (const float*)d_in[3];
    float* out = (float*)d_out;

    ir_mean_kernel<<<NIRB, 256>>>((const float4*)ir);
    fusion_main_kernel<<<NBLK, NT>>>(vis, ir, outp, mask);
    finalize_kernel<<<1, NT>>>(out);
}